// round 2
// baseline (speedup 1.0000x reference)
#include <cuda_runtime.h>
#include <math_constants.h>

// Problem constants
#define NB   4
#define CIN  256
#define CI   128
#define HW   4096

// ------------------------- scratch (static __device__, no allocs) ----------
__device__ float d_theta[NB * CI * HW];          // 8 MB
__device__ float d_phi  [NB * CI * HW];          // 8 MB
__device__ float d_g    [NB * CI * HW];          // 8 MB
__device__ float d_att  [NB * CI * HW];          // 8 MB
__device__ float d_S    [(size_t)NB * HW * HW];  // 256 MB (raw S, then P in-place)
__device__ float d_m    [NB * HW];
__device__ float d_rz   [NB * HW];

// ============================================================================
// K1: theta/phi/g projections.  O[n][k][p] = sum_c W[k][c] * x[n][c][p] + b[k]
// M=128(k), N=4096(p), K=256(c). BM=128, BN=128, BK=32, 256 thr, 8x8 microtile.
// grid = (32 p-tiles, 4 n, 3 proj)
// ============================================================================
__global__ __launch_bounds__(256)
void proj_kernel(const float* __restrict__ x,
                 const float* __restrict__ tw, const float* __restrict__ tb,
                 const float* __restrict__ pw, const float* __restrict__ pb,
                 const float* __restrict__ gw, const float* __restrict__ gb)
{
    const int jt = blockIdx.x, n = blockIdx.y, pr = blockIdx.z;
    const float* W; const float* B; float* O;
    if (pr == 0)      { W = tw; B = tb; O = d_theta; }
    else if (pr == 1) { W = pw; B = pb; O = d_phi;   }
    else              { W = gw; B = gb; O = d_g;     }
    O += n * CI * HW;
    const float* X = x + (size_t)n * CIN * HW + jt * 128;

    __shared__ float As[32][128];   // [k-chunk][m]
    __shared__ float Bs[32][128];   // [k-chunk][p]

    const int tid = threadIdx.x;
    const int tx = tid % 16, ty = tid / 16;

    float acc[8][8];
    #pragma unroll
    for (int i = 0; i < 8; i++)
        #pragma unroll
        for (int j = 0; j < 8; j++) acc[i][j] = 0.f;

    for (int k0 = 0; k0 < CIN; k0 += 32) {
        // W tile (128 x 32), row-major stride CIN -> transpose into As[k][m]
        #pragma unroll
        for (int l = 0; l < 4; l++) {
            int idx = tid + l * 256;
            int row = idx >> 3, kq = idx & 7;
            float4 v = *(const float4*)(W + row * CIN + k0 + kq * 4);
            As[kq*4+0][row] = v.x; As[kq*4+1][row] = v.y;
            As[kq*4+2][row] = v.z; As[kq*4+3][row] = v.w;
        }
        // X tile (32 x 128), direct
        #pragma unroll
        for (int l = 0; l < 4; l++) {
            int idx = tid + l * 256;
            int kk = idx >> 5, pq = idx & 31;
            *(float4*)&Bs[kk][pq*4] = *(const float4*)(X + (size_t)(k0+kk) * HW + pq * 4);
        }
        __syncthreads();
        #pragma unroll
        for (int kk = 0; kk < 32; kk++) {
            float a[8], b[8];
            *(float4*)(a)   = *(float4*)&As[kk][ty*4];
            *(float4*)(a+4) = *(float4*)&As[kk][64 + ty*4];
            *(float4*)(b)   = *(float4*)&Bs[kk][tx*4];
            *(float4*)(b+4) = *(float4*)&Bs[kk][64 + tx*4];
            #pragma unroll
            for (int i = 0; i < 8; i++)
                #pragma unroll
                for (int j = 0; j < 8; j++) acc[i][j] += a[i] * b[j];
        }
        __syncthreads();
    }
    #pragma unroll
    for (int r = 0; r < 8; r++) {
        int row = (r < 4) ? (ty*4 + r) : (64 + ty*4 + r - 4);
        float bias = B[row];
        float4 o0, o1;
        o0.x = acc[r][0]+bias; o0.y = acc[r][1]+bias; o0.z = acc[r][2]+bias; o0.w = acc[r][3]+bias;
        o1.x = acc[r][4]+bias; o1.y = acc[r][5]+bias; o1.z = acc[r][6]+bias; o1.w = acc[r][7]+bias;
        *(float4*)(O + (size_t)row * HW + jt*128 + tx*4)      = o0;
        *(float4*)(O + (size_t)row * HW + jt*128 + 64 + tx*4) = o1;
    }
}

// ============================================================================
// K2: S[n][i][j] = sum_c phi[n][c][i] * theta[n][c][j]  (both K-major: TN GEMM)
// Block owns 64 i-rows, sweeps all j in tiles of 128, keeps online (m, Z).
// Stores raw S; writes d_m, d_rz at the end.  grid = (64 i-tiles, 4 n).
// ============================================================================
__global__ __launch_bounds__(256)
void s_stats_kernel()
{
    const int it = blockIdx.x, n = blockIdx.y;
    const float* PHI = d_phi   + n * CI * HW + it * 64;
    const float* THE = d_theta + n * CI * HW;
    float* S = d_S + (size_t)n * HW * HW + (size_t)(it * 64) * HW;

    __shared__ float As[32][64];     // phi chunk  [c][i]   8 KB
    __shared__ float Bs[32][128];    // theta chunk[c][j]  16 KB
    __shared__ float redm[64][16];   //  4 KB
    __shared__ float redz[64][16];   //  4 KB

    const int tid = threadIdx.x;
    const int tx = tid % 16, ty = tid / 16;

    float m_run[4], z_run[4];
    #pragma unroll
    for (int r = 0; r < 4; r++) { m_run[r] = -CUDART_INF_F; z_run[r] = 0.f; }

    for (int jt = 0; jt < 32; jt++) {
        float acc[4][8];
        #pragma unroll
        for (int r = 0; r < 4; r++)
            #pragma unroll
            for (int c = 0; c < 8; c++) acc[r][c] = 0.f;

        for (int k0 = 0; k0 < CI; k0 += 32) {
            #pragma unroll
            for (int l = 0; l < 2; l++) {
                int idx = tid + l * 256;
                int kk = idx >> 4, iq = idx & 15;
                *(float4*)&As[kk][iq*4] = *(const float4*)(PHI + (size_t)(k0+kk) * HW + iq * 4);
            }
            #pragma unroll
            for (int l = 0; l < 4; l++) {
                int idx = tid + l * 256;
                int kk = idx >> 5, jq = idx & 31;
                *(float4*)&Bs[kk][jq*4] = *(const float4*)(THE + (size_t)(k0+kk) * HW + jt*128 + jq * 4);
            }
            __syncthreads();
            #pragma unroll
            for (int kk = 0; kk < 32; kk++) {
                float a[4], b[8];
                *(float4*)(a)   = *(float4*)&As[kk][ty*4];
                *(float4*)(b)   = *(float4*)&Bs[kk][tx*4];
                *(float4*)(b+4) = *(float4*)&Bs[kk][64 + tx*4];
                #pragma unroll
                for (int r = 0; r < 4; r++)
                    #pragma unroll
                    for (int c = 0; c < 8; c++) acc[r][c] += a[r] * b[c];
            }
            __syncthreads();
        }
        // store raw S tile + online stats update
        #pragma unroll
        for (int r = 0; r < 4; r++) {
            float* Sr = S + (size_t)(ty*4 + r) * HW + jt*128;
            *(float4*)(Sr + tx*4)      = *(float4*)&acc[r][0];
            *(float4*)(Sr + 64 + tx*4) = *(float4*)&acc[r][4];
            float tmax = acc[r][0];
            #pragma unroll
            for (int c = 1; c < 8; c++) tmax = fmaxf(tmax, acc[r][c]);
            float nm = fmaxf(m_run[r], tmax);
            float zs = 0.f;
            #pragma unroll
            for (int c = 0; c < 8; c++) zs += __expf(acc[r][c] - nm);
            z_run[r] = z_run[r] * __expf(m_run[r] - nm) + zs;
            m_run[r] = nm;
        }
    }
    #pragma unroll
    for (int r = 0; r < 4; r++) {
        redm[ty*4 + r][tx] = m_run[r];
        redz[ty*4 + r][tx] = z_run[r];
    }
    __syncthreads();
    if (tid < 64) {
        float m = -CUDART_INF_F;
        #pragma unroll
        for (int t = 0; t < 16; t++) m = fmaxf(m, redm[tid][t]);
        float z = 0.f;
        #pragma unroll
        for (int t = 0; t < 16; t++) z += redz[tid][t] * __expf(redm[tid][t] - m);
        d_m [n * HW + it*64 + tid] = m;
        d_rz[n * HW + it*64 + tid] = 1.0f / z;
    }
}

// ============================================================================
// K3: P = exp(S - m_i) * rz_i, in place.  One float4 per thread, exact grid.
// ============================================================================
__global__ __launch_bounds__(256)
void softmax_apply_kernel()
{
    size_t i4 = (size_t)blockIdx.x * blockDim.x + threadIdx.x;  // float4 index
    size_t base = i4 * 4;
    size_t row = base >> 12;               // (n*HW + i)
    float m  = d_m[row];
    float rz = d_rz[row];
    float4 v = *((float4*)d_S + i4);
    v.x = __expf(v.x - m) * rz;
    v.y = __expf(v.y - m) * rz;
    v.z = __expf(v.z - m) * rz;
    v.w = __expf(v.w - m) * rz;
    *((float4*)d_S + i4) = v;
}

// ============================================================================
// K4: att[n][c][j] = sum_i g[n][c][i] * P[n][i][j]
// M=128(c), N=4096(j), K=4096(i). BM=128, BN=64, BK=32, 8x4 microtile.
// grid = (64 j-tiles, 4 n)
// ============================================================================
__global__ __launch_bounds__(256)
void att_kernel()
{
    const int jt = blockIdx.x, n = blockIdx.y;
    const float* G = d_g + n * CI * HW;
    const float* P = d_S + (size_t)n * HW * HW;
    float* O = d_att + n * CI * HW;

    __shared__ float As[32][128];  // g chunk, transposed [k][c]
    __shared__ float Bs[32][64];   // P chunk [k][j]

    const int tid = threadIdx.x;
    const int tx = tid % 16, ty = tid / 16;

    float acc[8][4];
    #pragma unroll
    for (int i = 0; i < 8; i++)
        #pragma unroll
        for (int j = 0; j < 4; j++) acc[i][j] = 0.f;

    for (int k0 = 0; k0 < HW; k0 += 32) {
        #pragma unroll
        for (int l = 0; l < 4; l++) {
            int idx = tid + l * 256;
            int row = idx >> 3, kq = idx & 7;
            float4 v = *(const float4*)(G + (size_t)row * HW + k0 + kq * 4);
            As[kq*4+0][row] = v.x; As[kq*4+1][row] = v.y;
            As[kq*4+2][row] = v.z; As[kq*4+3][row] = v.w;
        }
        #pragma unroll
        for (int l = 0; l < 2; l++) {
            int idx = tid + l * 256;
            int kk = idx >> 4, jq = idx & 15;
            *(float4*)&Bs[kk][jq*4] = *(const float4*)(P + (size_t)(k0+kk) * HW + jt*64 + jq * 4);
        }
        __syncthreads();
        #pragma unroll
        for (int kk = 0; kk < 32; kk++) {
            float a[8], b[4];
            *(float4*)(a)   = *(float4*)&As[kk][ty*4];
            *(float4*)(a+4) = *(float4*)&As[kk][64 + ty*4];
            *(float4*)(b)   = *(float4*)&Bs[kk][tx*4];
            #pragma unroll
            for (int i = 0; i < 8; i++)
                #pragma unroll
                for (int j = 0; j < 4; j++) acc[i][j] += a[i] * b[j];
        }
        __syncthreads();
    }
    #pragma unroll
    for (int r = 0; r < 8; r++) {
        int row = (r < 4) ? (ty*4 + r) : (64 + ty*4 + r - 4);
        *(float4*)(O + (size_t)row * HW + jt*64 + tx*4) = *(float4*)&acc[r][0];
    }
}

// ============================================================================
// K5: out[n][co][j] = x[n][co][j] + w_b[co] + sum_ci w_w[co][ci]*att[n][ci][j]
// M=256 (2 tiles of 128), N=4096, K=128. grid = (32 j-tiles, 2 m-tiles, 4 n)
// ============================================================================
__global__ __launch_bounds__(256)
void out_kernel(const float* __restrict__ x,
                const float* __restrict__ ww, const float* __restrict__ wb,
                float* __restrict__ out)
{
    const int jt = blockIdx.x, mt = blockIdx.y, n = blockIdx.z;
    const float* A = ww + mt * 128 * CI;
    const float* B = d_att + n * CI * HW;

    __shared__ float As[32][128];
    __shared__ float Bs[32][128];

    const int tid = threadIdx.x;
    const int tx = tid % 16, ty = tid / 16;

    float acc[8][8];
    #pragma unroll
    for (int i = 0; i < 8; i++)
        #pragma unroll
        for (int j = 0; j < 8; j++) acc[i][j] = 0.f;

    for (int k0 = 0; k0 < CI; k0 += 32) {
        #pragma unroll
        for (int l = 0; l < 4; l++) {
            int idx = tid + l * 256;
            int row = idx >> 3, kq = idx & 7;
            float4 v = *(const float4*)(A + row * CI + k0 + kq * 4);
            As[kq*4+0][row] = v.x; As[kq*4+1][row] = v.y;
            As[kq*4+2][row] = v.z; As[kq*4+3][row] = v.w;
        }
        #pragma unroll
        for (int l = 0; l < 4; l++) {
            int idx = tid + l * 256;
            int kk = idx >> 5, jq = idx & 31;
            *(float4*)&Bs[kk][jq*4] = *(const float4*)(B + (size_t)(k0+kk) * HW + jt*128 + jq * 4);
        }
        __syncthreads();
        #pragma unroll
        for (int kk = 0; kk < 32; kk++) {
            float a[8], b[8];
            *(float4*)(a)   = *(float4*)&As[kk][ty*4];
            *(float4*)(a+4) = *(float4*)&As[kk][64 + ty*4];
            *(float4*)(b)   = *(float4*)&Bs[kk][tx*4];
            *(float4*)(b+4) = *(float4*)&Bs[kk][64 + tx*4];
            #pragma unroll
            for (int i = 0; i < 8; i++)
                #pragma unroll
                for (int j = 0; j < 8; j++) acc[i][j] += a[i] * b[j];
        }
        __syncthreads();
    }
    #pragma unroll
    for (int r = 0; r < 8; r++) {
        int row = (r < 4) ? (ty*4 + r) : (64 + ty*4 + r - 4);
        int gr = mt * 128 + row;
        float bias = wb[gr];
        const float* xr = x   + (size_t)n * CIN * HW + (size_t)gr * HW + jt*128;
        float*       orow = out + (size_t)n * CIN * HW + (size_t)gr * HW + jt*128;
        float4 x0 = *(const float4*)(xr + tx*4);
        float4 x1 = *(const float4*)(xr + 64 + tx*4);
        float4 o0, o1;
        o0.x = acc[r][0]+bias+x0.x; o0.y = acc[r][1]+bias+x0.y;
        o0.z = acc[r][2]+bias+x0.z; o0.w = acc[r][3]+bias+x0.w;
        o1.x = acc[r][4]+bias+x1.x; o1.y = acc[r][5]+bias+x1.y;
        o1.z = acc[r][6]+bias+x1.z; o1.w = acc[r][7]+bias+x1.w;
        *(float4*)(orow + tx*4)      = o0;
        *(float4*)(orow + 64 + tx*4) = o1;
    }
}

// ============================================================================
extern "C" void kernel_launch(void* const* d_in, const int* in_sizes, int n_in,
                              void* d_out, int out_size)
{
    const float* x  = (const float*)d_in[0];
    const float* tw = (const float*)d_in[1];
    const float* tb = (const float*)d_in[2];
    const float* pw = (const float*)d_in[3];
    const float* pb = (const float*)d_in[4];
    const float* gw = (const float*)d_in[5];
    const float* gb = (const float*)d_in[6];
    const float* ww = (const float*)d_in[7];
    const float* wb = (const float*)d_in[8];
    float* out = (float*)d_out;

    proj_kernel<<<dim3(32, 4, 3), 256>>>(x, tw, tb, pw, pb, gw, gb);
    s_stats_kernel<<<dim3(64, 4), 256>>>();
    // 4*4096*4096 floats / 4 per thread / 256 threads = 65536 blocks (exact)
    softmax_apply_kernel<<<65536, 256>>>();
    att_kernel<<<dim3(64, 4), 256>>>();
    out_kernel<<<dim3(32, 2, 4), 256>>>(x, ww, wb, out);
}

// round 4
// speedup vs baseline: 2.6781x; 2.6781x over previous
#include <cuda_runtime.h>
#include <cuda_fp16.h>
#include <math_constants.h>
#include <cstdint>

#define NB   4
#define CIN  256
#define CI   128
#define HW   4096

// ---------------- helpers ----------------
__device__ __forceinline__ uint32_t smem_u32(const void* p) {
    uint32_t a;
    asm("{ .reg .u64 t; cvta.to.shared.u64 t, %1; cvt.u32.u64 %0, t; }" : "=r"(a) : "l"(p));
    return a;
}
__device__ __forceinline__ void ldsm4(uint32_t* r, uint32_t addr) {
    asm volatile("ldmatrix.sync.aligned.m8n8.x4.shared.b16 {%0,%1,%2,%3}, [%4];"
        : "=r"(r[0]), "=r"(r[1]), "=r"(r[2]), "=r"(r[3]) : "r"(addr));
}
__device__ __forceinline__ void mma_f16(float* c, const uint32_t* a, const uint32_t* b) {
    asm volatile("mma.sync.aligned.m16n8k16.row.col.f32.f16.f16.f32 "
        "{%0,%1,%2,%3}, {%4,%5,%6,%7}, {%8,%9}, {%0,%1,%2,%3};"
        : "+f"(c[0]), "+f"(c[1]), "+f"(c[2]), "+f"(c[3])
        : "r"(a[0]), "r"(a[1]), "r"(a[2]), "r"(a[3]), "r"(b[0]), "r"(b[1]));
}
__device__ __forceinline__ unsigned short f2h(float v) {
    return __half_as_ushort(__float2half_rn(v));
}
__device__ __forceinline__ float h2f(unsigned short u) {
    return __half2float(__ushort_as_half(u));
}

// ---------------- scratch ----------------
__device__ __align__(16) unsigned short d_th[NB * HW * CI];  // theta^T hi [n][p][c]
__device__ __align__(16) unsigned short d_tl[NB * HW * CI];  // theta^T lo
__device__ __align__(16) unsigned short d_fh[NB * HW * CI];  // phi^T hi
__device__ __align__(16) unsigned short d_fl[NB * HW * CI];  // phi^T lo
__device__ __align__(16) unsigned short d_gh[NB * CI * HW];  // g hi [n][c][p]
__device__ float d_S  [(size_t)NB * HW * HW];                // S^T [n][j][i]
__device__ float d_pm [NB * 32 * HW];
__device__ float d_pz [NB * 32 * HW];
__device__ float d_m  [NB * HW];
__device__ float d_rz [NB * HW];
__device__ float d_att[NB * CI * HW];

// ============================================================================
// K1: projections (fp32 SIMT) -> fp16 hi/lo; theta/phi transposed, g natural
// ============================================================================
__global__ __launch_bounds__(256)
void proj_kernel(const float* __restrict__ x,
                 const float* __restrict__ tw, const float* __restrict__ tb,
                 const float* __restrict__ pw, const float* __restrict__ pb,
                 const float* __restrict__ gw, const float* __restrict__ gb)
{
    const int jt = blockIdx.x, n = blockIdx.y, pr = blockIdx.z;
    const float *W, *B;
    if (pr == 0)      { W = tw; B = tb; }
    else if (pr == 1) { W = pw; B = pb; }
    else              { W = gw; B = gb; }
    const float* X = x + (size_t)n * CIN * HW + jt * 128;

    __shared__ float As[32][128];
    __shared__ float Bs[32][128];
    const int tid = threadIdx.x, tx = tid % 16, ty = tid / 16;

    float acc[8][8];
    #pragma unroll
    for (int i = 0; i < 8; i++)
        #pragma unroll
        for (int j = 0; j < 8; j++) acc[i][j] = 0.f;

    for (int k0 = 0; k0 < CIN; k0 += 32) {
        #pragma unroll
        for (int l = 0; l < 4; l++) {
            int idx = tid + l * 256, row = idx >> 3, kq = idx & 7;
            float4 v = *(const float4*)(W + row * CIN + k0 + kq * 4);
            As[kq*4+0][row] = v.x; As[kq*4+1][row] = v.y;
            As[kq*4+2][row] = v.z; As[kq*4+3][row] = v.w;
        }
        #pragma unroll
        for (int l = 0; l < 4; l++) {
            int idx = tid + l * 256, kk = idx >> 5, pq = idx & 31;
            *(float4*)&Bs[kk][pq*4] = *(const float4*)(X + (size_t)(k0+kk) * HW + pq * 4);
        }
        __syncthreads();
        #pragma unroll
        for (int kk = 0; kk < 32; kk++) {
            float a[8], b[8];
            *(float4*)(a)   = *(float4*)&As[kk][ty*4];
            *(float4*)(a+4) = *(float4*)&As[kk][64 + ty*4];
            *(float4*)(b)   = *(float4*)&Bs[kk][tx*4];
            *(float4*)(b+4) = *(float4*)&Bs[kk][64 + tx*4];
            #pragma unroll
            for (int i = 0; i < 8; i++)
                #pragma unroll
                for (int j = 0; j < 8; j++) acc[i][j] += a[i] * b[j];
        }
        __syncthreads();
    }
    #pragma unroll
    for (int r = 0; r < 8; r++) {
        int k = (r < 4) ? (ty*4 + r) : (64 + ty*4 + r - 4);
        float bias = B[k];
        #pragma unroll
        for (int c = 0; c < 8; c++) acc[r][c] += bias;
    }

    if (pr < 2) {
        unsigned short* Hh = (pr == 0) ? d_th : d_fh;
        unsigned short* Ll = (pr == 0) ? d_tl : d_fl;
        #pragma unroll
        for (int c = 0; c < 8; c++) {
            int p = (c < 4) ? (tx*4 + c) : (64 + tx*4 + c - 4);
            size_t ro = ((size_t)(n * HW + jt * 128 + p)) * 128;
            #pragma unroll
            for (int kh = 0; kh < 2; kh++) {
                int kb = kh ? (64 + ty*4) : (ty*4);
                ushort4 H, L;
                float v0 = acc[kh*4+0][c], v1 = acc[kh*4+1][c];
                float v2 = acc[kh*4+2][c], v3 = acc[kh*4+3][c];
                H.x = f2h(v0); H.y = f2h(v1); H.z = f2h(v2); H.w = f2h(v3);
                L.x = f2h(v0 - h2f(H.x)); L.y = f2h(v1 - h2f(H.y));
                L.z = f2h(v2 - h2f(H.z)); L.w = f2h(v3 - h2f(H.w));
                *(ushort4*)(Hh + ro + kb) = H;
                *(ushort4*)(Ll + ro + kb) = L;
            }
        }
    } else {
        #pragma unroll
        for (int r = 0; r < 8; r++) {
            int k = (r < 4) ? (ty*4 + r) : (64 + ty*4 + r - 4);
            size_t ro = ((size_t)(n * CI + k)) * HW + jt * 128;
            #pragma unroll
            for (int ph = 0; ph < 2; ph++) {
                int pb2 = ph ? (64 + tx*4) : (tx*4);
                ushort4 H;
                H.x = f2h(acc[r][ph*4+0]); H.y = f2h(acc[r][ph*4+1]);
                H.z = f2h(acc[r][ph*4+2]); H.w = f2h(acc[r][ph*4+3]);
                *(ushort4*)(d_gh + ro + pb2) = H;
            }
        }
    }
}

// ============================================================================
// K2: S^T[j][i] = sum_c theta^T[j][c] * phi^T[i][c]  via mma.sync fp16 split
// Block: 128(j) x 128(i), K=128 in 2 chunks of 64. 8 warps, warp tile 32x64.
// Fused epilogue: S tile store + per-i partial softmax stats over 128 j rows.
// grid = (it 32, jt 32, n 4)
// ============================================================================
#define SLDA 72                   // halfword row stride of operand tiles
#define STILE 18432               // 128*72*2 bytes per tile
#define S_DYN (4 * STILE)         // 73728

__global__ __launch_bounds__(256, 2)
void s_gemm()
{
    extern __shared__ char sm[];
    const int it = blockIdx.x, jt = blockIdx.y, n = blockIdx.z;
    const int tid = threadIdx.x, wid = tid >> 5, lane = tid & 31;
    const int wm = wid & 3, wn = wid >> 2;      // warp tile: rows j 32, cols i 64
    const uint32_t sb = smem_u32(sm);
    const uint32_t AH = 0, AL = STILE, BH = 2*STILE, BL = 3*STILE;

    __shared__ float s_pm[2][128], s_pz[2][128];

    float acc[2][8][4];
    #pragma unroll
    for (int a = 0; a < 2; a++)
        #pragma unroll
        for (int b = 0; b < 8; b++)
            #pragma unroll
            for (int c = 0; c < 4; c++) acc[a][b][c] = 0.f;

    const int g = lane >> 3, lr = lane & 7;

    for (int kc = 0; kc < 2; kc++) {
        #pragma unroll
        for (int l = 0; l < 4; l++) {
            int u = tid + l * 256, r = u >> 3, k8 = u & 7;
            uint32_t doff = (uint32_t)(r * SLDA + k8 * 8) * 2;
            size_t ao = ((size_t)(n * HW + jt * 128 + r)) * 128 + kc * 64 + k8 * 8;
            size_t bo = ((size_t)(n * HW + it * 128 + r)) * 128 + kc * 64 + k8 * 8;
            *(uint4*)(sm + AH + doff) = *(const uint4*)(d_th + ao);
            *(uint4*)(sm + AL + doff) = *(const uint4*)(d_tl + ao);
            *(uint4*)(sm + BH + doff) = *(const uint4*)(d_fh + bo);
            *(uint4*)(sm + BL + doff) = *(const uint4*)(d_fl + bo);
        }
        __syncthreads();

        #pragma unroll
        for (int ks = 0; ks < 4; ks++) {
            const int k0 = ks * 16;
            uint32_t ah[2][4], al[2][4];
            #pragma unroll
            for (int ma = 0; ma < 2; ma++) {
                int row = wm * 32 + ma * 16 + (g & 1) * 8 + lr;
                int col = k0 + (g >> 1) * 8;
                uint32_t ad = sb + AH + (uint32_t)(row * SLDA + col) * 2;
                ldsm4(ah[ma], ad);
                ldsm4(al[ma], ad + STILE);
            }
            #pragma unroll
            for (int np = 0; np < 4; np++) {
                int nrow = wn * 64 + np * 16 + (g >> 1) * 8 + lr;
                int ncol = k0 + (g & 1) * 8;
                uint32_t bd = sb + BH + (uint32_t)(nrow * SLDA + ncol) * 2;
                uint32_t b[4];
                ldsm4(b, bd);            // B_hi: frags np*2, np*2+1
                mma_f16(acc[0][np*2],   ah[0], b);
                mma_f16(acc[1][np*2],   ah[1], b);
                mma_f16(acc[0][np*2+1], ah[0], b+2);
                mma_f16(acc[1][np*2+1], ah[1], b+2);
                mma_f16(acc[0][np*2],   al[0], b);
                mma_f16(acc[1][np*2],   al[1], b);
                mma_f16(acc[0][np*2+1], al[0], b+2);
                mma_f16(acc[1][np*2+1], al[1], b+2);
                ldsm4(b, bd + STILE);    // B_lo
                mma_f16(acc[0][np*2],   ah[0], b);
                mma_f16(acc[1][np*2],   ah[1], b);
                mma_f16(acc[0][np*2+1], ah[0], b+2);
                mma_f16(acc[1][np*2+1], ah[1], b+2);
            }
        }
        __syncthreads();
    }

    // ---- epilogue: frags -> smem fp32 buf [128][132] ----
    float* buf = (float*)sm;
    #pragma unroll
    for (int ma = 0; ma < 2; ma++) {
        int r0 = wm * 32 + ma * 16 + (lane >> 2);
        #pragma unroll
        for (int nb = 0; nb < 8; nb++) {
            int c0 = wn * 64 + nb * 8 + 2 * (lane & 3);
            buf[r0 * 132 + c0]       = acc[ma][nb][0];
            buf[r0 * 132 + c0 + 1]   = acc[ma][nb][1];
            buf[(r0+8) * 132 + c0]   = acc[ma][nb][2];
            buf[(r0+8) * 132 + c0+1] = acc[ma][nb][3];
        }
    }
    __syncthreads();

    // S tile -> gmem
    #pragma unroll
    for (int l = 0; l < 16; l++) {
        int u = tid + l * 256, r = u >> 5, q = u & 31;
        size_t go = (size_t)n * HW * HW + (size_t)(jt * 128 + r) * HW + it * 128 + q * 4;
        *(float4*)(d_S + go) = *(float4*)(buf + r * 132 + q * 4);
    }
    // partial stats per column i over 128 j rows
    {
        int i = tid & 127, hf = tid >> 7;
        float mx = -CUDART_INF_F;
        #pragma unroll 4
        for (int r = 0; r < 64; r++) mx = fmaxf(mx, buf[(hf * 64 + r) * 132 + i]);
        float z = 0.f;
        #pragma unroll 4
        for (int r = 0; r < 64; r++) z += __expf(buf[(hf * 64 + r) * 132 + i] - mx);
        s_pm[hf][i] = mx; s_pz[hf][i] = z;
    }
    __syncthreads();
    if (tid < 128) {
        float m0 = s_pm[0][tid], m1 = s_pm[1][tid];
        float m = fmaxf(m0, m1);
        float z = s_pz[0][tid] * __expf(m0 - m) + s_pz[1][tid] * __expf(m1 - m);
        size_t po = ((size_t)(n * 32 + jt)) * HW + it * 128 + tid;
        d_pm[po] = m; d_pz[po] = z;
    }
}

// ============================================================================
// K3: combine 32 partials -> d_m, d_rz
// ============================================================================
__global__ __launch_bounds__(256)
void stat_combine()
{
    int idx = blockIdx.x * 256 + threadIdx.x;
    int n = idx >> 12, i = idx & 4095;
    float m = -CUDART_INF_F;
    #pragma unroll
    for (int t = 0; t < 32; t++)
        m = fmaxf(m, d_pm[((size_t)(n * 32 + t)) * HW + i]);
    float z = 0.f;
    #pragma unroll
    for (int t = 0; t < 32; t++) {
        size_t o = ((size_t)(n * 32 + t)) * HW + i;
        z += d_pz[o] * __expf(d_pm[o] - m);
    }
    d_m[n * HW + i]  = m;
    d_rz[n * HW + i] = 1.0f / z;
}

// ============================================================================
// K4: att[c][j] = sum_i g[c][i] * P^T[j][i], exp fused into B staging
// Block: 128(c) x 64(j), K=4096 in 64 chunks. 8 warps, warp tile 32x32.
// grid = (jt 64, n 4)
// ============================================================================
#define ALDA 72
#define GT_BYTES (128 * ALDA * 2)        // 18432
#define PT_OFF   GT_BYTES
#define ATT_DYN  (128 * 68 * 4)          // 34816 (epilogue buf dominates)

__global__ __launch_bounds__(256, 2)
void att_gemm()
{
    extern __shared__ char sm[];
    const int jt = blockIdx.x, n = blockIdx.y;
    const int tid = threadIdx.x, wid = tid >> 5, lane = tid & 31;
    const int wm = wid & 3, wn = wid >> 2;    // warp tile: c 32 x j 32
    const uint32_t sb = smem_u32(sm);
    __shared__ float sm_m[64], sm_rz[64];

    float acc[2][4][4];
    #pragma unroll
    for (int a = 0; a < 2; a++)
        #pragma unroll
        for (int b = 0; b < 4; b++)
            #pragma unroll
            for (int c = 0; c < 4; c++) acc[a][b][c] = 0.f;

    const int g = lane >> 3, lr = lane & 7;

    for (int kc = 0; kc < 64; kc++) {
        if (tid < 64) {
            sm_m [tid] = d_m [n * HW + kc * 64 + tid];
            sm_rz[tid] = d_rz[n * HW + kc * 64 + tid];
        }
        __syncthreads();

        // A: g_hi, 128 c-rows x 64 i
        #pragma unroll
        for (int l = 0; l < 4; l++) {
            int u = tid + l * 256, r = u >> 3, k8 = u & 7;
            size_t go = ((size_t)(n * CI + r)) * HW + kc * 64 + k8 * 8;
            *(uint4*)(sm + (uint32_t)(r * ALDA + k8 * 8) * 2) = *(const uint4*)(d_gh + go);
        }
        // B: P^T rows jt*64.., fused exp, fp32 -> fp16
        #pragma unroll
        for (int l = 0; l < 4; l++) {
            int u = tid + l * 256, r = u >> 4, q = u & 15;
            const float* s = d_S + (size_t)n * HW * HW
                           + (size_t)(jt * 64 + r) * HW + kc * 64 + q * 4;
            float4 v = *(const float4*)s;
            ushort4 h;
            h.x = f2h(__expf(v.x - sm_m[q*4+0]) * sm_rz[q*4+0]);
            h.y = f2h(__expf(v.y - sm_m[q*4+1]) * sm_rz[q*4+1]);
            h.z = f2h(__expf(v.z - sm_m[q*4+2]) * sm_rz[q*4+2]);
            h.w = f2h(__expf(v.w - sm_m[q*4+3]) * sm_rz[q*4+3]);
            *(ushort4*)(sm + PT_OFF + (uint32_t)(r * ALDA + q * 4) * 2) = h;
        }
        __syncthreads();

        #pragma unroll
        for (int ks = 0; ks < 4; ks++) {
            const int k0 = ks * 16;
            uint32_t ah[2][4];
            #pragma unroll
            for (int ma = 0; ma < 2; ma++) {
                int row = wm * 32 + ma * 16 + (g & 1) * 8 + lr;
                int col = k0 + (g >> 1) * 8;
                ldsm4(ah[ma], sb + (uint32_t)(row * ALDA + col) * 2);
            }
            #pragma unroll
            for (int np = 0; np < 2; np++) {
                int nrow = wn * 32 + np * 16 + (g >> 1) * 8 + lr;
                int ncol = k0 + (g & 1) * 8;
                uint32_t b[4];
                ldsm4(b, sb + PT_OFF + (uint32_t)(nrow * ALDA + ncol) * 2);
                mma_f16(acc[0][np*2],   ah[0], b);
                mma_f16(acc[1][np*2],   ah[1], b);
                mma_f16(acc[0][np*2+1], ah[0], b+2);
                mma_f16(acc[1][np*2+1], ah[1], b+2);
            }
        }
        __syncthreads();
    }

    // epilogue: frags -> buf [128][68] -> d_att
    float* buf = (float*)sm;
    #pragma unroll
    for (int ma = 0; ma < 2; ma++) {
        int r0 = wm * 32 + ma * 16 + (lane >> 2);
        #pragma unroll
        for (int nb = 0; nb < 4; nb++) {
            int c0 = wn * 32 + nb * 8 + 2 * (lane & 3);
            buf[r0 * 68 + c0]       = acc[ma][nb][0];
            buf[r0 * 68 + c0 + 1]   = acc[ma][nb][1];
            buf[(r0+8) * 68 + c0]   = acc[ma][nb][2];
            buf[(r0+8) * 68 + c0+1] = acc[ma][nb][3];
        }
    }
    __syncthreads();
    #pragma unroll
    for (int l = 0; l < 8; l++) {
        int u = tid + l * 256, r = u >> 4, q = u & 15;
        *(float4*)(d_att + ((size_t)(n * CI + r)) * HW + jt * 64 + q * 4)
            = *(float4*)(buf + r * 68 + q * 4);
    }
}

// ============================================================================
// K5: out = x + W*att + b   (fp32 SIMT)
// ============================================================================
__global__ __launch_bounds__(256)
void out_kernel(const float* __restrict__ x,
                const float* __restrict__ ww, const float* __restrict__ wb,
                float* __restrict__ out)
{
    const int jt = blockIdx.x, mt = blockIdx.y, n = blockIdx.z;
    const float* A = ww + mt * 128 * CI;
    const float* B = d_att + (size_t)n * CI * HW;

    __shared__ float As[32][128];
    __shared__ float Bs[32][128];
    const int tid = threadIdx.x, tx = tid % 16, ty = tid / 16;

    float acc[8][8];
    #pragma unroll
    for (int i = 0; i < 8; i++)
        #pragma unroll
        for (int j = 0; j < 8; j++) acc[i][j] = 0.f;

    for (int k0 = 0; k0 < CI; k0 += 32) {
        #pragma unroll
        for (int l = 0; l < 4; l++) {
            int idx = tid + l * 256, row = idx >> 3, kq = idx & 7;
            float4 v = *(const float4*)(A + row * CI + k0 + kq * 4);
            As[kq*4+0][row] = v.x; As[kq*4+1][row] = v.y;
            As[kq*4+2][row] = v.z; As[kq*4+3][row] = v.w;
        }
        #pragma unroll
        for (int l = 0; l < 4; l++) {
            int idx = tid + l * 256, kk = idx >> 5, jq = idx & 31;
            *(float4*)&Bs[kk][jq*4] = *(const float4*)(B + (size_t)(k0+kk) * HW + jt*128 + jq * 4);
        }
        __syncthreads();
        #pragma unroll
        for (int kk = 0; kk < 32; kk++) {
            float a[8], b[8];
            *(float4*)(a)   = *(float4*)&As[kk][ty*4];
            *(float4*)(a+4) = *(float4*)&As[kk][64 + ty*4];
            *(float4*)(b)   = *(float4*)&Bs[kk][tx*4];
            *(float4*)(b+4) = *(float4*)&Bs[kk][64 + tx*4];
            #pragma unroll
            for (int i = 0; i < 8; i++)
                #pragma unroll
                for (int j = 0; j < 8; j++) acc[i][j] += a[i] * b[j];
        }
        __syncthreads();
    }
    #pragma unroll
    for (int r = 0; r < 8; r++) {
        int row = (r < 4) ? (ty*4 + r) : (64 + ty*4 + r - 4);
        int gr = mt * 128 + row;
        float bias = wb[gr];
        const float* xr = x + (size_t)n * CIN * HW + (size_t)gr * HW + jt*128;
        float* orow = out + (size_t)n * CIN * HW + (size_t)gr * HW + jt*128;
        float4 x0 = *(const float4*)(xr + tx*4);
        float4 x1 = *(const float4*)(xr + 64 + tx*4);
        float4 o0, o1;
        o0.x = acc[r][0]+bias+x0.x; o0.y = acc[r][1]+bias+x0.y;
        o0.z = acc[r][2]+bias+x0.z; o0.w = acc[r][3]+bias+x0.w;
        o1.x = acc[r][4]+bias+x1.x; o1.y = acc[r][5]+bias+x1.y;
        o1.z = acc[r][6]+bias+x1.z; o1.w = acc[r][7]+bias+x1.w;
        *(float4*)(orow + tx*4)      = o0;
        *(float4*)(orow + 64 + tx*4) = o1;
    }
}

// ============================================================================
extern "C" void kernel_launch(void* const* d_in, const int* in_sizes, int n_in,
                              void* d_out, int out_size)
{
    const float* x  = (const float*)d_in[0];
    const float* tw = (const float*)d_in[1];
    const float* tb = (const float*)d_in[2];
    const float* pw = (const float*)d_in[3];
    const float* pb = (const float*)d_in[4];
    const float* gw = (const float*)d_in[5];
    const float* gb = (const float*)d_in[6];
    const float* ww = (const float*)d_in[7];
    const float* wb = (const float*)d_in[8];
    float* out = (float*)d_out;

    cudaFuncSetAttribute(s_gemm,   cudaFuncAttributeMaxDynamicSharedMemorySize, S_DYN);
    cudaFuncSetAttribute(att_gemm, cudaFuncAttributeMaxDynamicSharedMemorySize, ATT_DYN);

    proj_kernel<<<dim3(32, 4, 3), 256>>>(x, tw, tb, pw, pb, gw, gb);
    s_gemm<<<dim3(32, 32, 4), 256, S_DYN>>>();
    stat_combine<<<64, 256>>>();
    att_gemm<<<dim3(64, 4), 256, ATT_DYN>>>();
    out_kernel<<<dim3(32, 2, 4), 256>>>(x, ww, wb, out);
}